// round 1
// baseline (speedup 1.0000x reference)
#include <cuda_runtime.h>
#include <cstddef>

// Problem constants (from reference)
#define BATCH   16
#define IN_CH   2
#define FDIM    2048
#define TDIM    1024
#define NBANDS  64
#define BANDSZ  32      // FDIM / NBANDS
#define EMB     128

#define T_CHUNK 256
#define THREADS 256

__global__ __launch_bounds__(THREADS)
void bandsplit_kernel(const float* __restrict__ x,
                      const float* __restrict__ W,
                      const float* __restrict__ bias,
                      float* __restrict__ out)
{
    __shared__ float xm0[T_CHUNK];
    __shared__ float xm1[T_CHUNK];

    const int g  = blockIdx.x;
    const int tc = g & 3;               // t-chunk index (TDIM / T_CHUNK = 4)
    const int n  = (g >> 2) & 63;       // band
    const int b  = g >> 8;              // batch
    const int t0 = tc * T_CHUNK;
    const int tid = threadIdx.x;

    // ---------------- Phase 1: band mean over 32 f-rows, both channels ------
    // x index: ((b*IN_CH + c)*FDIM + f)*TDIM + t
    const size_t ft = (size_t)FDIM * TDIM;             // 2,097,152
    const float* xp0 = x + (size_t)b * IN_CH * ft
                         + (size_t)(n * BANDSZ) * TDIM
                         + t0 + tid;
    const float* xp1 = xp0 + ft;

    float s0 = 0.f, s1 = 0.f;
    #pragma unroll
    for (int f = 0; f < BANDSZ; f++) s0 += xp0[(size_t)f * TDIM];
    #pragma unroll
    for (int f = 0; f < BANDSZ; f++) s1 += xp1[(size_t)f * TDIM];

    xm0[tid] = s0 * (1.f / BANDSZ);
    xm1[tid] = s1 * (1.f / BANDSZ);
    __syncthreads();

    // ---------------- Phase 2: project to EMB and write ---------------------
    // thread layout: e4 = (tid % 32) -> owns 4 consecutive emb elements,
    //                trow = tid / 32 -> 8 t-rows per iteration
    const int e4   = (tid & 31) * 4;
    const int trow = tid >> 5;

    const float4 w0 = *(const float4*)(W + ((size_t)n * IN_CH + 0) * EMB + e4);
    const float4 w1 = *(const float4*)(W + ((size_t)n * IN_CH + 1) * EMB + e4);
    const float4 bb = *(const float4*)(bias + (size_t)n * EMB + e4);

    // out index: ((b*NBANDS + n)*TDIM + t)*EMB + e
    float4* op = (float4*)(out + (((size_t)b * NBANDS + n) * TDIM + t0) * EMB + e4);

    #pragma unroll 4
    for (int i = 0; i < T_CHUNK / 8; i++) {
        const int t = trow + i * 8;
        const float m0 = xm0[t];   // warp-uniform -> smem broadcast
        const float m1 = xm1[t];
        float4 r;
        r.x = fmaf(m0, w0.x, fmaf(m1, w1.x, bb.x));
        r.y = fmaf(m0, w0.y, fmaf(m1, w1.y, bb.y));
        r.z = fmaf(m0, w0.z, fmaf(m1, w1.z, bb.z));
        r.w = fmaf(m0, w0.w, fmaf(m1, w1.w, bb.w));
        op[(size_t)t * (EMB / 4)] = r;
    }
}

extern "C" void kernel_launch(void* const* d_in, const int* in_sizes, int n_in,
                              void* d_out, int out_size)
{
    const float* x    = (const float*)d_in[0];
    const float* W    = (const float*)d_in[1];
    const float* bias = (const float*)d_in[2];
    float* out        = (float*)d_out;

    const int grid = BATCH * NBANDS * (TDIM / T_CHUNK);  // 4096
    bandsplit_kernel<<<grid, THREADS>>>(x, W, bias, out);
}